// round 10
// baseline (speedup 1.0000x reference)
#include <cuda_runtime.h>
#include <cstdint>
#include <math_constants.h>

#define NN    169343
#define EMAX  2600000
#define EPSV  1e-5f
#define NB_SCAN ((NN + 1023) / 1024)   // 166
#define GY1   1324                     // cdiv(NN,128) for layer-1 GEMM grid.y

// ---------------- scratch (static device globals; no allocs) ----------------
__device__ int   g_src[EMAX];
__device__ int   g_dst[EMAX];
__device__ int   g_cnt[NN];
__device__ int   g_cur[NN];
__device__ int   g_rowptr[NN];
__device__ int   g_bsum[NB_SCAN];
__device__ float g_dinv[NN];
__device__ float g_snorm[NN];
__device__ int   g_csr_src[EMAX];
__device__ float g_csr_w[EMAX];
__device__ float g_bufA[(size_t)NN * 256];
__device__ float g_bufB[(size_t)NN * 256];
__device__ float g_buf40[(size_t)NN * 40];
__device__ int   g_is64;

static inline int cdiv(long a, long b) { return (int)((a + b - 1) / b); }

// ---------------- SGEMM body (128x64 tile, BK=16, 256 thr, 8x4 micro) ------
__device__ __forceinline__ void sgemm_body(
    const float* __restrict__ A, const float* __restrict__ W,
    float* __restrict__ C, int M, int K, int Ncol, int by)
{
    __shared__ float As[16][129];
    __shared__ float Bs[16][64];

    const int tid = threadIdx.x;
    const int bm = by * 128;
    const int bn = blockIdx.x * 64;
    const int ry = tid >> 4;
    const int cx = tid & 15;

    float acc[8][4];
#pragma unroll
    for (int i = 0; i < 8; i++)
#pragma unroll
        for (int j = 0; j < 4; j++) acc[i][j] = 0.f;

    for (int k0 = 0; k0 < K; k0 += 16) {
#pragma unroll
        for (int l = 0; l < 2; l++) {
            int idx = tid + l * 256;
            int r  = idx >> 2;
            int c4 = (idx & 3) << 2;
            int grow = bm + r;
            float4 v = make_float4(0.f, 0.f, 0.f, 0.f);
            if (grow < M) v = *(const float4*)&A[(size_t)grow * K + k0 + c4];
            As[c4 + 0][r] = v.x; As[c4 + 1][r] = v.y;
            As[c4 + 2][r] = v.z; As[c4 + 3][r] = v.w;
        }
        {
            int r  = tid >> 4;
            int c4 = (tid & 15) << 2;
            int gc = bn + c4;
            float4 v = make_float4(0.f, 0.f, 0.f, 0.f);
            if (gc < Ncol) v = *(const float4*)&W[(size_t)(k0 + r) * Ncol + gc];
            *(float4*)&Bs[r][c4] = v;
        }
        __syncthreads();
#pragma unroll
        for (int k = 0; k < 16; k++) {
            float a[8];
#pragma unroll
            for (int i = 0; i < 8; i++) a[i] = As[k][ry + (i << 4)];
            float4 bv = *(const float4*)&Bs[k][cx << 2];
#pragma unroll
            for (int i = 0; i < 8; i++) {
                acc[i][0] += a[i] * bv.x;
                acc[i][1] += a[i] * bv.y;
                acc[i][2] += a[i] * bv.z;
                acc[i][3] += a[i] * bv.w;
            }
        }
        __syncthreads();
    }

    int colbase = bn + (cx << 2);
    if (colbase >= Ncol) return;
#pragma unroll
    for (int i = 0; i < 8; i++) {
        int row = bm + ry + (i << 4);
        if (row < M) {
            float4 o = make_float4(acc[i][0], acc[i][1], acc[i][2], acc[i][3]);
            *(float4*)&C[(size_t)row * Ncol + colbase] = o;
        }
    }
}

// launch 0: layer-1 GEMM fused with cnt/cur zeroing + dtype detect (tail blocks)
__global__ __launch_bounds__(256) void k_gemm1_zero(
    const float* __restrict__ A, const float* __restrict__ W,
    float* __restrict__ C, const long long* __restrict__ ei)
{
    if (blockIdx.y >= GY1) {
        if (blockIdx.x != 0) return;
        int b = blockIdx.y - GY1;
        int base = b * 1024 + threadIdx.x * 4;
#pragma unroll
        for (int j = 0; j < 4; j++) {
            int i = base + j;
            if (i < NN) { g_cnt[i] = 0; g_cur[i] = 0; }
        }
        if (b == 0 && threadIdx.x == 0) {
            int ok = 1;
            for (int i = 0; i < 64; i++) {
                long long v = ei[i];
                if (v < 0 || v >= NN) { ok = 0; break; }
            }
            g_is64 = ok;
        }
        return;
    }
    sgemm_body(A, W, C, NN, 128, 256, blockIdx.y);
}

__global__ __launch_bounds__(256) void k_sgemm(
    const float* __restrict__ A, const float* __restrict__ W,
    float* __restrict__ C, int M, int K, int Ncol)
{
    sgemm_body(A, W, C, M, K, Ncol, blockIdx.y);
}

// ---------------- prep ----------------
__global__ void k_count(const void* __restrict__ ei, int E) {
    int e = blockIdx.x * blockDim.x + threadIdx.x;
    if (e >= E) return;
    long long s, d;
    if (g_is64) {
        const long long* p = (const long long*)ei;
        s = p[e]; d = p[(size_t)E + e];
    } else {
        const int* p = (const int*)ei;
        s = p[e]; d = p[(size_t)E + e];
    }
    if ((unsigned long long)s < (unsigned long long)NN &&
        (unsigned long long)d < (unsigned long long)NN) {
        g_src[e] = (int)s; g_dst[e] = (int)d;
        atomicAdd(&g_cnt[(int)d], 1);
    } else {
        g_src[e] = -1; g_dst[e] = -1;
    }
}

__global__ void k_scan1() {
    __shared__ int sh[256];
    int b = blockIdx.x, t = threadIdx.x;
    int base = b * 1024 + t * 4;
    int v[4];
#pragma unroll
    for (int j = 0; j < 4; j++) v[j] = (base + j < NN) ? g_cnt[base + j] : 0;
    int ts = v[0] + v[1] + v[2] + v[3];
    sh[t] = ts;
    __syncthreads();
#pragma unroll
    for (int off = 1; off < 256; off <<= 1) {
        int x = (t >= off) ? sh[t - off] : 0;
        __syncthreads();
        sh[t] += x;
        __syncthreads();
    }
    int run = sh[t] - ts;
#pragma unroll
    for (int j = 0; j < 4; j++) {
        if (base + j < NN) g_rowptr[base + j] = run;
        run += v[j];
    }
    if (t == 255) g_bsum[b] = sh[255];
}

// scan2 fused into scan3: every block redundantly scans the 166 block sums.
__global__ void k_scan23_norms() {
    __shared__ int sh[256];
    int t = threadIdx.x;
    sh[t] = (t < NB_SCAN) ? g_bsum[t] : 0;
    __syncthreads();
#pragma unroll
    for (int off = 1; off < 256; off <<= 1) {
        int x = (t >= off) ? sh[t - off] : 0;
        __syncthreads();
        sh[t] += x;
        __syncthreads();
    }
    int add = (blockIdx.x == 0) ? 0 : sh[blockIdx.x - 1];   // exclusive prefix
    int base = blockIdx.x * 1024 + t * 4;
#pragma unroll
    for (int j = 0; j < 4; j++) {
        int i = base + j;
        if (i < NN) {
            g_rowptr[i] += add;
            float deg = (float)(g_cnt[i] + 1);
            g_dinv[i]  = rsqrtf(deg);
            g_snorm[i] = 1.0f / deg;
        }
    }
}

__global__ void k_fill(int E) {
    int e = blockIdx.x * blockDim.x + threadIdx.x;
    if (e >= E) return;
    int d = g_dst[e];
    if (d < 0) return;
    int s = g_src[e];
    int slot = g_rowptr[d] + atomicAdd(&g_cur[d], 1);
    g_csr_src[slot] = s;
    g_csr_w[slot]   = g_dinv[s] * g_dinv[d];
}

// -------- aggregation over a 128-feature half (L2-resident working set) ----
// Y[n, col] = relu( (agg + self + bias - mean) * g*rsqrt(var+eps) + beta )
//          = relu( (agg + self) * sc + sf )
template <int H>
__global__ __launch_bounds__(256) void k_agg128(
    const float* __restrict__ X, float* __restrict__ Y,
    const float* __restrict__ bias,
    const float* __restrict__ gamma, const float* __restrict__ beta,
    const float* __restrict__ mean,  const float* __restrict__ var)
{
    int node = (int)((blockIdx.x * 256 + threadIdx.x) >> 5);
    int lane = threadIdx.x & 31;
    if (node >= NN) return;
    int start = g_rowptr[node];
    int cnt   = g_cnt[node];
    int col   = H * 128 + lane * 4;

    float4 g4 = *(const float4*)&gamma[col];
    float4 b4 = *(const float4*)&beta[col];
    float4 m4 = *(const float4*)&mean[col];
    float4 v4 = *(const float4*)&var[col];
    float4 bi = *(const float4*)&bias[col];
    float4 sc, sf;
    sc.x = g4.x * rsqrtf(v4.x + EPSV);  sf.x = b4.x + (bi.x - m4.x) * sc.x;
    sc.y = g4.y * rsqrtf(v4.y + EPSV);  sf.y = b4.y + (bi.y - m4.y) * sc.y;
    sc.z = g4.z * rsqrtf(v4.z + EPSV);  sf.z = b4.z + (bi.z - m4.z) * sc.z;
    sc.w = g4.w * rsqrtf(v4.w + EPSV);  sf.w = b4.w + (bi.w - m4.w) * sc.w;

    const float* Xh = X + H * 128 + lane * 4;
    float4 a = make_float4(0.f, 0.f, 0.f, 0.f);

    int   s0 = (cnt > 0) ? g_csr_src[start] : 0;
    float w0 = (cnt > 0) ? g_csr_w[start]   : 0.f;
#pragma unroll 2
    for (int i = 0; i < cnt; i++) {
        int   s1 = 0; float w1 = 0.f;
        if (i + 1 < cnt) { s1 = g_csr_src[start + i + 1]; w1 = g_csr_w[start + i + 1]; }
        float4 v = *(const float4*)(Xh + (size_t)s0 * 256);
        a.x += v.x * w0; a.y += v.y * w0; a.z += v.z * w0; a.w += v.w * w0;
        s0 = s1; w0 = w1;
    }
    {
        float sn = g_snorm[node];
        float4 v = *(const float4*)(Xh + (size_t)node * 256);
        a.x += v.x * sn; a.y += v.y * sn; a.z += v.z * sn; a.w += v.w * sn;
    }
    float4 o;
    o.x = fmaxf(a.x * sc.x + sf.x, 0.f);
    o.y = fmaxf(a.y * sc.y + sf.y, 0.f);
    o.z = fmaxf(a.z * sc.z + sf.z, 0.f);
    o.w = fmaxf(a.w * sc.w + sf.w, 0.f);
    *(float4*)(Y + (size_t)node * 256 + col) = o;
}

// ---------------- layer-3 aggregation + bias + log_softmax (warp/node) -----
__global__ void k_agg40_lsm(const float* __restrict__ X, float* __restrict__ out,
                            const float* __restrict__ b3) {
    int node = (int)((blockIdx.x * 256 + threadIdx.x) >> 5);
    int lane = threadIdx.x & 31;
    if (node >= NN) return;
    int start = g_rowptr[node];
    int cnt   = g_cnt[node];

    float a0 = 0.f, a1 = 0.f;
    for (int i = 0; i < cnt; i++) {
        int   s = g_csr_src[start + i];
        float w = g_csr_w[start + i];
        const float* xs = X + (size_t)s * 40;
        a0 += xs[lane] * w;
        if (lane < 8) a1 += xs[lane + 32] * w;
    }
    {
        float sn = g_snorm[node];
        const float* xd = X + (size_t)node * 40;
        a0 += xd[lane] * sn;
        if (lane < 8) a1 += xd[lane + 32] * sn;
    }
    a0 += b3[lane];
    if (lane < 8) a1 += b3[lane + 32];

    float v1 = (lane < 8) ? a1 : -CUDART_INF_F;
    float mx = fmaxf(a0, v1);
#pragma unroll
    for (int o = 16; o > 0; o >>= 1) mx = fmaxf(mx, __shfl_xor_sync(0xffffffffu, mx, o));
    float sum = expf(a0 - mx) + ((lane < 8) ? expf(a1 - mx) : 0.f);
#pragma unroll
    for (int o = 16; o > 0; o >>= 1) sum += __shfl_xor_sync(0xffffffffu, sum, o);
    float lg = mx + logf(sum);
    out[(size_t)node * 40 + lane] = a0 - lg;
    if (lane < 8) out[(size_t)node * 40 + lane + 32] = a1 - lg;
}

// ---------------- launch ----------------
extern "C" void kernel_launch(void* const* d_in, const int* in_sizes, int n_in,
                              void* d_out, int out_size) {
    const float* x   = (const float*)d_in[0];
    const void*  ei  = d_in[1];
    const float* W1  = (const float*)d_in[2];
    const float* b1  = (const float*)d_in[3];
    const float* g1  = (const float*)d_in[4];
    const float* be1 = (const float*)d_in[5];
    const float* m1  = (const float*)d_in[6];
    const float* v1  = (const float*)d_in[7];
    const float* W2  = (const float*)d_in[8];
    const float* b2  = (const float*)d_in[9];
    const float* g2  = (const float*)d_in[10];
    const float* be2 = (const float*)d_in[11];
    const float* m2  = (const float*)d_in[12];
    const float* v2  = (const float*)d_in[13];
    const float* W3  = (const float*)d_in[14];
    const float* b3  = (const float*)d_in[15];

    int E = in_sizes[1] / 2;
    if (E > EMAX) E = EMAX;

    float* out = (float*)d_out;
    float* emb;
    if ((long)out_size >= (long)NN * 296) {
        emb = out + (size_t)NN * 40;   // (out[N,40], emb[N,256]) concatenated
    } else {
        void* p = nullptr;
        cudaGetSymbolAddress(&p, g_bufB);
        emb = (float*)p;
    }

    const int warpsGrid = cdiv((long)NN * 32, 256);

    // 0: layer-1 GEMM + zero(cnt,cur) + dtype detect
    k_gemm1_zero<<<dim3(4, GY1 + NB_SCAN), 256>>>(x, W1, g_bufA, (const long long*)ei);
    // 1-4: CSR construction
    k_count<<<cdiv(E, 256), 256>>>(ei, E);
    k_scan1<<<NB_SCAN, 256>>>();
    k_scan23_norms<<<NB_SCAN, 256>>>();
    k_fill<<<cdiv(E, 256), 256>>>(E);

    // 5-6: layer-1 aggregation (two 128-feature halves; idx 5 is profiled)
    k_agg128<0><<<warpsGrid, 256>>>(g_bufA, g_bufB, b1, g1, be1, m1, v1);
    k_agg128<1><<<warpsGrid, 256>>>(g_bufA, g_bufB, b1, g1, be1, m1, v1);

    // 7-9: layer 2
    k_sgemm<<<dim3(4, GY1), 256>>>(g_bufB, W2, g_bufA, NN, 256, 256);
    k_agg128<0><<<warpsGrid, 256>>>(g_bufA, emb, b2, g2, be2, m2, v2);
    k_agg128<1><<<warpsGrid, 256>>>(g_bufA, emb, b2, g2, be2, m2, v2);

    // 10-11: layer 3
    k_sgemm<<<dim3(1, GY1), 256>>>(emb, W3, g_buf40, NN, 256, 40);
    k_agg40_lsm<<<warpsGrid, 256>>>(g_buf40, out, b3);
}

// round 13
// speedup vs baseline: 1.1710x; 1.1710x over previous
#include <cuda_runtime.h>
#include <cstdint>
#include <math_constants.h>

#define NN    169343
#define EMAX  2600000
#define EPSV  1e-5f
#define NB_SCAN ((NN + 1023) / 1024)   // 166
#define GY1   1324                     // cdiv(NN,128)

// ---------------- scratch (static device globals; no allocs) ----------------
__device__ int   g_src[EMAX];
__device__ int   g_dst[EMAX];
__device__ int   g_cnt[NN];
__device__ int   g_cur[NN];
__device__ int   g_rowptr[NN];
__device__ int   g_bsum[NB_SCAN];
__device__ float g_dinv[NN];
__device__ float g_snorm[NN];
__device__ int   g_csr_src[EMAX];
__device__ float g_csr_w[EMAX];
__device__ float g_bufA[(size_t)NN * 256];
__device__ float g_bufB[(size_t)NN * 256];
__device__ float g_buf40[(size_t)NN * 40];
__device__ int   g_is64;

static inline int cdiv(long a, long b) { return (int)((a + b - 1) / b); }

// ---------------- SGEMM body (128x64 tile, BK=16, 256 thr, 8x4 micro) ------
__device__ __forceinline__ void sgemm_body(
    const float* __restrict__ A, const float* __restrict__ W,
    float* __restrict__ C, int M, int K, int Ncol, int by)
{
    __shared__ float As[16][129];
    __shared__ float Bs[16][64];

    const int tid = threadIdx.x;
    const int bm = by * 128;
    const int bn = blockIdx.x * 64;
    const int ry = tid >> 4;
    const int cx = tid & 15;

    float acc[8][4];
#pragma unroll
    for (int i = 0; i < 8; i++)
#pragma unroll
        for (int j = 0; j < 4; j++) acc[i][j] = 0.f;

    for (int k0 = 0; k0 < K; k0 += 16) {
#pragma unroll
        for (int l = 0; l < 2; l++) {
            int idx = tid + l * 256;
            int r  = idx >> 2;
            int c4 = (idx & 3) << 2;
            int grow = bm + r;
            float4 v = make_float4(0.f, 0.f, 0.f, 0.f);
            if (grow < M) v = *(const float4*)&A[(size_t)grow * K + k0 + c4];
            As[c4 + 0][r] = v.x; As[c4 + 1][r] = v.y;
            As[c4 + 2][r] = v.z; As[c4 + 3][r] = v.w;
        }
        {
            int r  = tid >> 4;
            int c4 = (tid & 15) << 2;
            int gc = bn + c4;
            float4 v = make_float4(0.f, 0.f, 0.f, 0.f);
            if (gc < Ncol) v = *(const float4*)&W[(size_t)(k0 + r) * Ncol + gc];
            *(float4*)&Bs[r][c4] = v;
        }
        __syncthreads();
#pragma unroll
        for (int k = 0; k < 16; k++) {
            float a[8];
#pragma unroll
            for (int i = 0; i < 8; i++) a[i] = As[k][ry + (i << 4)];
            float4 bv = *(const float4*)&Bs[k][cx << 2];
#pragma unroll
            for (int i = 0; i < 8; i++) {
                acc[i][0] += a[i] * bv.x;
                acc[i][1] += a[i] * bv.y;
                acc[i][2] += a[i] * bv.z;
                acc[i][3] += a[i] * bv.w;
            }
        }
        __syncthreads();
    }

    int colbase = bn + (cx << 2);
    if (colbase >= Ncol) return;
#pragma unroll
    for (int i = 0; i < 8; i++) {
        int row = bm + ry + (i << 4);
        if (row < M) {
            float4 o = make_float4(acc[i][0], acc[i][1], acc[i][2], acc[i][3]);
            *(float4*)&C[(size_t)row * Ncol + colbase] = o;
        }
    }
}

// launch 0: layer-1 GEMM fused with cnt/cur zeroing + dtype detect (tail blocks)
__global__ __launch_bounds__(256) void k_gemm1_zero(
    const float* __restrict__ A, const float* __restrict__ W,
    float* __restrict__ C, const long long* __restrict__ ei)
{
    if (blockIdx.y >= GY1) {
        if (blockIdx.x != 0) return;
        int b = blockIdx.y - GY1;
        int base = b * 1024 + threadIdx.x * 4;
#pragma unroll
        for (int j = 0; j < 4; j++) {
            int i = base + j;
            if (i < NN) { g_cnt[i] = 0; g_cur[i] = 0; }
        }
        if (b == 0 && threadIdx.x == 0) {
            int ok = 1;
            for (int i = 0; i < 64; i++) {
                long long v = ei[i];
                if (v < 0 || v >= NN) { ok = 0; break; }
            }
            g_is64 = ok;
        }
        return;
    }
    sgemm_body(A, W, C, NN, 128, 256, blockIdx.y);
}

__global__ __launch_bounds__(256) void k_sgemm(
    const float* __restrict__ A, const float* __restrict__ W,
    float* __restrict__ C, int M, int K, int Ncol)
{
    sgemm_body(A, W, C, M, K, Ncol, blockIdx.y);
}

// ---------------- prep ----------------
__global__ void k_count(const void* __restrict__ ei, int E) {
    int e = blockIdx.x * blockDim.x + threadIdx.x;
    if (e >= E) return;
    long long s, d;
    if (g_is64) {
        const long long* p = (const long long*)ei;
        s = p[e]; d = p[(size_t)E + e];
    } else {
        const int* p = (const int*)ei;
        s = p[e]; d = p[(size_t)E + e];
    }
    if ((unsigned long long)s < (unsigned long long)NN &&
        (unsigned long long)d < (unsigned long long)NN) {
        g_src[e] = (int)s; g_dst[e] = (int)d;
        atomicAdd(&g_cnt[(int)d], 1);
    } else {
        g_src[e] = -1; g_dst[e] = -1;
    }
}

__global__ void k_scan1() {
    __shared__ int sh[256];
    int b = blockIdx.x, t = threadIdx.x;
    int base = b * 1024 + t * 4;
    int v[4];
#pragma unroll
    for (int j = 0; j < 4; j++) v[j] = (base + j < NN) ? g_cnt[base + j] : 0;
    int ts = v[0] + v[1] + v[2] + v[3];
    sh[t] = ts;
    __syncthreads();
#pragma unroll
    for (int off = 1; off < 256; off <<= 1) {
        int x = (t >= off) ? sh[t - off] : 0;
        __syncthreads();
        sh[t] += x;
        __syncthreads();
    }
    int run = sh[t] - ts;
#pragma unroll
    for (int j = 0; j < 4; j++) {
        if (base + j < NN) g_rowptr[base + j] = run;
        run += v[j];
    }
    if (t == 255) g_bsum[b] = sh[255];
}

__global__ void k_scan23_norms() {
    __shared__ int sh[256];
    int t = threadIdx.x;
    sh[t] = (t < NB_SCAN) ? g_bsum[t] : 0;
    __syncthreads();
#pragma unroll
    for (int off = 1; off < 256; off <<= 1) {
        int x = (t >= off) ? sh[t - off] : 0;
        __syncthreads();
        sh[t] += x;
        __syncthreads();
    }
    int add = (blockIdx.x == 0) ? 0 : sh[blockIdx.x - 1];
    int base = blockIdx.x * 1024 + t * 4;
#pragma unroll
    for (int j = 0; j < 4; j++) {
        int i = base + j;
        if (i < NN) {
            g_rowptr[i] += add;
            float deg = (float)(g_cnt[i] + 1);
            g_dinv[i]  = rsqrtf(deg);
            g_snorm[i] = 1.0f / deg;
        }
    }
}

__global__ void k_fill(int E) {
    int e = blockIdx.x * blockDim.x + threadIdx.x;
    if (e >= E) return;
    int d = g_dst[e];
    if (d < 0) return;
    int s = g_src[e];
    int slot = g_rowptr[d] + atomicAdd(&g_cur[d], 1);
    g_csr_src[slot] = s;
    g_csr_w[slot]   = g_dinv[s] * g_dinv[d];
}

// -------- aggregation, warp per node, 4-deep neighbor ILP, fused BN+ReLU ---
__global__ __launch_bounds__(256) void k_agg256(
    const float* __restrict__ X, float* __restrict__ Y,
    const float* __restrict__ bias,
    const float* __restrict__ gamma, const float* __restrict__ beta,
    const float* __restrict__ mean,  const float* __restrict__ var)
{
    int node = (int)((blockIdx.x * 256 + threadIdx.x) >> 5);
    int lane = threadIdx.x & 31;
    if (node >= NN) return;
    int start = g_rowptr[node];
    int cnt   = g_cnt[node];
    int col0  = lane * 4;           // features col0..col0+3 and col0+128..+131

    float4 a0 = make_float4(0.f, 0.f, 0.f, 0.f);
    float4 a1 = make_float4(0.f, 0.f, 0.f, 0.f);

    int i = 0;
    for (; i + 4 <= cnt; i += 4) {
        int   s[4]; float w[4];
#pragma unroll
        for (int j = 0; j < 4; j++) {
            s[j] = g_csr_src[start + i + j];
            w[j] = g_csr_w[start + i + j];
        }
        float4 v0[4], v1[4];
#pragma unroll
        for (int j = 0; j < 4; j++) {
            const float* xs = X + (size_t)s[j] * 256 + col0;
            v0[j] = *(const float4*)xs;
            v1[j] = *(const float4*)(xs + 128);
        }
#pragma unroll
        for (int j = 0; j < 4; j++) {
            a0.x += v0[j].x * w[j]; a0.y += v0[j].y * w[j];
            a0.z += v0[j].z * w[j]; a0.w += v0[j].w * w[j];
            a1.x += v1[j].x * w[j]; a1.y += v1[j].y * w[j];
            a1.z += v1[j].z * w[j]; a1.w += v1[j].w * w[j];
        }
    }
    for (; i < cnt; i++) {
        int   s = g_csr_src[start + i];
        float w = g_csr_w[start + i];
        const float* xs = X + (size_t)s * 256 + col0;
        float4 v0 = *(const float4*)xs;
        float4 v1 = *(const float4*)(xs + 128);
        a0.x += v0.x * w; a0.y += v0.y * w; a0.z += v0.z * w; a0.w += v0.w * w;
        a1.x += v1.x * w; a1.y += v1.y * w; a1.z += v1.z * w; a1.w += v1.w * w;
    }
    {
        float sn = g_snorm[node];
        const float* xd = X + (size_t)node * 256 + col0;
        float4 v0 = *(const float4*)xd;
        float4 v1 = *(const float4*)(xd + 128);
        a0.x += v0.x * sn; a0.y += v0.y * sn; a0.z += v0.z * sn; a0.w += v0.w * sn;
        a1.x += v1.x * sn; a1.y += v1.y * sn; a1.z += v1.z * sn; a1.w += v1.w * sn;
    }

    // epilogue: (a + bias - mean)*g*rsqrt(var+eps) + beta, relu
#pragma unroll
    for (int h = 0; h < 2; h++) {
        int col = col0 + h * 128;
        float4* ap = h ? &a1 : &a0;
        float4 g4 = *(const float4*)&gamma[col];
        float4 b4 = *(const float4*)&beta[col];
        float4 m4 = *(const float4*)&mean[col];
        float4 v4 = *(const float4*)&var[col];
        float4 bi = *(const float4*)&bias[col];
        float scx = g4.x * rsqrtf(v4.x + EPSV);
        float scy = g4.y * rsqrtf(v4.y + EPSV);
        float scz = g4.z * rsqrtf(v4.z + EPSV);
        float scw = g4.w * rsqrtf(v4.w + EPSV);
        float4 o;
        o.x = fmaxf((ap->x + bi.x - m4.x) * scx + b4.x, 0.f);
        o.y = fmaxf((ap->y + bi.y - m4.y) * scy + b4.y, 0.f);
        o.z = fmaxf((ap->z + bi.z - m4.z) * scz + b4.z, 0.f);
        o.w = fmaxf((ap->w + bi.w - m4.w) * scw + b4.w, 0.f);
        *(float4*)(Y + (size_t)node * 256 + col) = o;
    }
}

// ------- layer-3 aggregation + bias + log_softmax, 8-deep neighbor ILP -----
__global__ void k_agg40_lsm(const float* __restrict__ X, float* __restrict__ out,
                            const float* __restrict__ b3) {
    int node = (int)((blockIdx.x * 256 + threadIdx.x) >> 5);
    int lane = threadIdx.x & 31;
    if (node >= NN) return;
    int start = g_rowptr[node];
    int cnt   = g_cnt[node];

    float a0 = 0.f, a1 = 0.f;
    int i = 0;
    for (; i + 8 <= cnt; i += 8) {
        int   s[8]; float w[8];
#pragma unroll
        for (int j = 0; j < 8; j++) {
            s[j] = g_csr_src[start + i + j];
            w[j] = g_csr_w[start + i + j];
        }
        float u0[8], u1[8];
#pragma unroll
        for (int j = 0; j < 8; j++) {
            const float* xs = X + (size_t)s[j] * 40;
            u0[j] = xs[lane];
            u1[j] = (lane < 8) ? xs[lane + 32] : 0.f;
        }
#pragma unroll
        for (int j = 0; j < 8; j++) { a0 += u0[j] * w[j]; a1 += u1[j] * w[j]; }
    }
    for (; i < cnt; i++) {
        int   s = g_csr_src[start + i];
        float w = g_csr_w[start + i];
        const float* xs = X + (size_t)s * 40;
        a0 += xs[lane] * w;
        if (lane < 8) a1 += xs[lane + 32] * w;
    }
    {
        float sn = g_snorm[node];
        const float* xd = X + (size_t)node * 40;
        a0 += xd[lane] * sn;
        if (lane < 8) a1 += xd[lane + 32] * sn;
    }
    a0 += b3[lane];
    if (lane < 8) a1 += b3[lane + 32];

    float v1 = (lane < 8) ? a1 : -CUDART_INF_F;
    float mx = fmaxf(a0, v1);
#pragma unroll
    for (int o = 16; o > 0; o >>= 1) mx = fmaxf(mx, __shfl_xor_sync(0xffffffffu, mx, o));
    float sum = expf(a0 - mx) + ((lane < 8) ? expf(a1 - mx) : 0.f);
#pragma unroll
    for (int o = 16; o > 0; o >>= 1) sum += __shfl_xor_sync(0xffffffffu, sum, o);
    float lg = mx + logf(sum);
    out[(size_t)node * 40 + lane] = a0 - lg;
    if (lane < 8) out[(size_t)node * 40 + lane + 32] = a1 - lg;
}

// ---------------- launch ----------------
extern "C" void kernel_launch(void* const* d_in, const int* in_sizes, int n_in,
                              void* d_out, int out_size) {
    const float* x   = (const float*)d_in[0];
    const void*  ei  = d_in[1];
    const float* W1  = (const float*)d_in[2];
    const float* b1  = (const float*)d_in[3];
    const float* g1  = (const float*)d_in[4];
    const float* be1 = (const float*)d_in[5];
    const float* m1  = (const float*)d_in[6];
    const float* v1  = (const float*)d_in[7];
    const float* W2  = (const float*)d_in[8];
    const float* b2  = (const float*)d_in[9];
    const float* g2  = (const float*)d_in[10];
    const float* be2 = (const float*)d_in[11];
    const float* m2  = (const float*)d_in[12];
    const float* v2  = (const float*)d_in[13];
    const float* W3  = (const float*)d_in[14];
    const float* b3  = (const float*)d_in[15];

    int E = in_sizes[1] / 2;
    if (E > EMAX) E = EMAX;

    float* out = (float*)d_out;
    float* emb;
    if ((long)out_size >= (long)NN * 296) {
        emb = out + (size_t)NN * 40;   // (out[N,40], emb[N,256]) concatenated
    } else {
        void* p = nullptr;
        cudaGetSymbolAddress(&p, g_bufB);
        emb = (float*)p;
    }

    const int warpsGrid = cdiv((long)NN * 32, 256);

    // 0: layer-1 GEMM + zero + detect (single launch; unsliced)
    k_gemm1_zero<<<dim3(4, GY1 + NB_SCAN), 256>>>(x, W1, g_bufA, (const long long*)ei);
    // 1-4: CSR construction
    k_count<<<cdiv(E, 256), 256>>>(ei, E);
    k_scan1<<<NB_SCAN, 256>>>();
    k_scan23_norms<<<NB_SCAN, 256>>>();
    k_fill<<<cdiv(E, 256), 256>>>(E);

    // 5: layer-1 aggregation (full 256 features, ILP-batched)
    k_agg256<<<warpsGrid, 256>>>(g_bufA, g_bufB, b1, g1, be1, m1, v1);

    // 6-7: layer 2
    k_sgemm<<<dim3(4, GY1), 256>>>(g_bufB, W2, g_bufA, NN, 256, 256);
    k_agg256<<<warpsGrid, 256>>>(g_bufA, emb, b2, g2, be2, m2, v2);

    // 8-9: layer 3
    k_sgemm<<<dim3(1, GY1), 256>>>(emb, W3, g_buf40, NN, 256, 40);
    k_agg40_lsm<<<warpsGrid, 256>>>(g_buf40, out, b3);
}